// round 1
// baseline (speedup 1.0000x reference)
#include <cuda_runtime.h>
#include <cstdint>

// Problem shape (fixed by the dataset)
#define Bc   8
#define Ac   16384
#define Sc   2048
#define Dc   512
#define OUTc 512

// ---------------- scratch (device globals; no allocation allowed) ----------
__device__ float g_pooled[Bc * Sc * Dc];   // 32 MB pooled [B,S,D]
__device__ float g_avgsum[Bc * Dc];        // per-protein sum over filled residues
__device__ int   g_filled[Bc * Sc];
__device__ int   g_nfill[Bc];

// ---------------- helpers --------------------------------------------------
__device__ __forceinline__ uint32_t f2tf(float x) {
    uint32_t r;
    asm("cvt.rna.tf32.f32 %0, %1;" : "=r"(r) : "f"(x));
    return r;
}

#define MMA_TF32(c0, c1, c2, c3, a0, a1, a2, a3, b0, b1)                      \
    asm volatile(                                                             \
        "mma.sync.aligned.m16n8k8.row.col.f32.tf32.tf32.f32 "                 \
        "{%0,%1,%2,%3}, {%4,%5,%6,%7}, {%8,%9}, {%0,%1,%2,%3};"               \
        : "+f"(c0), "+f"(c1), "+f"(c2), "+f"(c3)                              \
        : "r"(a0), "r"(a1), "r"(a2), "r"(a3), "r"(b0), "r"(b1))

// ---------------- kernel 0: zero the accumulators (graph replays!) ---------
__global__ void zero_kernel() {
    int i = blockIdx.x * blockDim.x + threadIdx.x;
    if (i < Bc * Dc) g_avgsum[i] = 0.0f;
    if (i < Bc) g_nfill[i] = 0;
}

// ---------------- kernel 1: segment-mean pooling ---------------------------
// One block per (b, s). Atoms with residue id s are contiguous (ids sorted).
__global__ void pool_kernel(const float* __restrict__ rep,
                            const int* __restrict__ ids,
                            const int* __restrict__ aa_len,
                            const int* __restrict__ seq_len) {
    int bs = blockIdx.x;
    int b = bs / Sc, s = bs % Sc;
    int L = aa_len[b];
    const int* p = ids + b * Ac;

    // all threads do the same search (uniform -> broadcast loads)
    int lo = 0, hi = L;
    while (lo < hi) { int mid = (lo + hi) >> 1; if (p[mid] < s) lo = mid + 1; else hi = mid; }
    int start = lo;
    hi = L;
    while (lo < hi) { int mid = (lo + hi) >> 1; if (p[mid] <= s) lo = mid + 1; else hi = mid; }
    int end = lo;
    int cnt = end - start;

    int t = threadIdx.x;  // 128 threads x float4 = 512 cols
    const float4* base = reinterpret_cast<const float4*>(rep) + (size_t)b * Ac * (Dc / 4);
    float4 acc = make_float4(0.f, 0.f, 0.f, 0.f);
    int a = start;
    // unroll-by-2 for a bit of MLP
    for (; a + 1 < end; a += 2) {
        float4 v0 = base[(size_t)a * (Dc / 4) + t];
        float4 v1 = base[(size_t)(a + 1) * (Dc / 4) + t];
        acc.x += v0.x + v1.x; acc.y += v0.y + v1.y;
        acc.z += v0.z + v1.z; acc.w += v0.w + v1.w;
    }
    if (a < end) {
        float4 v0 = base[(size_t)a * (Dc / 4) + t];
        acc.x += v0.x; acc.y += v0.y; acc.z += v0.z; acc.w += v0.w;
    }
    float inv = 1.0f / (float)(cnt > 0 ? cnt : 1);
    acc.x *= inv; acc.y *= inv; acc.z *= inv; acc.w *= inv;
    reinterpret_cast<float4*>(g_pooled)[(size_t)bs * (Dc / 4) + t] = acc;
    if (t == 0) g_filled[bs] = (cnt > 0 && s < seq_len[b]) ? 1 : 0;
}

// ---------------- kernel 2: sum pooled over filled residues ----------------
#define SCH 64
__global__ void avg_kernel() {
    int blk = blockIdx.x;
    int b = blk / (Sc / SCH);
    int s0 = (blk % (Sc / SCH)) * SCH;
    int t = threadIdx.x;  // 128 threads x float4
    const float4* p4 = reinterpret_cast<const float4*>(g_pooled);
    float4 acc = make_float4(0.f, 0.f, 0.f, 0.f);
    int nf = 0;
    for (int i = 0; i < SCH; i++) {
        int r = b * Sc + s0 + i;
        if (g_filled[r]) {
            float4 v = p4[(size_t)r * (Dc / 4) + t];
            acc.x += v.x; acc.y += v.y; acc.z += v.z; acc.w += v.w;
            nf++;
        }
    }
    atomicAdd(&g_avgsum[b * Dc + t * 4 + 0], acc.x);
    atomicAdd(&g_avgsum[b * Dc + t * 4 + 1], acc.y);
    atomicAdd(&g_avgsum[b * Dc + t * 4 + 2], acc.z);
    atomicAdd(&g_avgsum[b * Dc + t * 4 + 3], acc.w);
    if (t == 0) atomicAdd(&g_nfill[b], nf);
}

// ---------------- kernel 3: fill unfilled rows -----------------------------
__global__ void fill_kernel(const int* __restrict__ seq_len) {
    int r = blockIdx.x;
    if (g_filled[r]) return;  // vast majority
    int b = r / Sc, s = r % Sc;
    int t = threadIdx.x;
    float4 v = make_float4(0.f, 0.f, 0.f, 0.f);
    if (s < seq_len[b]) {
        int nf = g_nfill[b];
        float inv = 1.0f / (float)(nf > 0 ? nf : 1);
        v.x = g_avgsum[b * Dc + t * 4 + 0] * inv;
        v.y = g_avgsum[b * Dc + t * 4 + 1] * inv;
        v.z = g_avgsum[b * Dc + t * 4 + 2] * inv;
        v.w = g_avgsum[b * Dc + t * 4 + 3] * inv;
    }
    reinterpret_cast<float4*>(g_pooled)[(size_t)r * (Dc / 4) + t] = v;
}

// ---------------- kernel 4: GEMM out = pooled @ W^T + bias (tf32 mma) ------
// M = B*S = 16384, N = OUT = 512, K = D = 512.
#define BM 128
#define BN 64
#define BK 16
#define GEMM_THREADS 256

__global__ __launch_bounds__(GEMM_THREADS)
void gemm_kernel(const float* __restrict__ Wm, const float* __restrict__ bias,
                 float* __restrict__ out) {
    __shared__ float As[2][BM][BK + 4];  // stride 20 floats: 16B aligned, conflict-free frags
    __shared__ float Bs[2][BN][BK + 4];

    const int tid = threadIdx.x;
    const int bm = blockIdx.x, bn = blockIdx.y;

    const float* Aori = g_pooled + (size_t)bm * BM * Dc;
    const float* Bori = Wm + (size_t)bn * BN * Dc;

    const int warp = tid >> 5, lane = tid & 31;
    const int wm = warp & 3, wn = warp >> 2;      // 4 x 2 warp grid
    const int m_off = wm * 32, n_off = wn * 32;   // 32x32 warp tile
    const int lr = lane >> 2, lc = lane & 3;

    float c[2][4][4];
#pragma unroll
    for (int mi = 0; mi < 2; mi++)
#pragma unroll
        for (int ni = 0; ni < 4; ni++)
#pragma unroll
            for (int j = 0; j < 4; j++) c[mi][ni][j] = 0.f;

    auto load_tile = [&](int kt, int buf) {
        int k0 = kt * BK;
#pragma unroll
        for (int i = 0; i < 2; i++) {  // A: 512 float4 chunks
            int idx = tid + i * 256;
            int row = idx >> 2, c4 = idx & 3;
            const float* src = Aori + row * Dc + k0 + c4 * 4;
            uint32_t dst = (uint32_t)__cvta_generic_to_shared(&As[buf][row][c4 * 4]);
            asm volatile("cp.async.ca.shared.global [%0], [%1], 16;" ::"r"(dst), "l"(src));
        }
        {  // B: 256 float4 chunks
            int row = tid >> 2, c4 = tid & 3;
            const float* src = Bori + row * Dc + k0 + c4 * 4;
            uint32_t dst = (uint32_t)__cvta_generic_to_shared(&Bs[buf][row][c4 * 4]);
            asm volatile("cp.async.ca.shared.global [%0], [%1], 16;" ::"r"(dst), "l"(src));
        }
    };

    const int KT = Dc / BK;  // 32
    int buf = 0;
    load_tile(0, 0);
    asm volatile("cp.async.commit_group;");

    for (int kt = 0; kt < KT; kt++) {
        if (kt + 1 < KT) load_tile(kt + 1, buf ^ 1);
        asm volatile("cp.async.commit_group;");
        asm volatile("cp.async.wait_group 1;");
        __syncthreads();

#pragma unroll
        for (int ks = 0; ks < 2; ks++) {
            int k0 = ks * 8;
            uint32_t a[2][4], bb[4][2];
#pragma unroll
            for (int mi = 0; mi < 2; mi++) {
                int r0 = m_off + mi * 16 + lr;
                a[mi][0] = f2tf(As[buf][r0][k0 + lc]);
                a[mi][1] = f2tf(As[buf][r0 + 8][k0 + lc]);
                a[mi][2] = f2tf(As[buf][r0][k0 + lc + 4]);
                a[mi][3] = f2tf(As[buf][r0 + 8][k0 + lc + 4]);
            }
#pragma unroll
            for (int ni = 0; ni < 4; ni++) {
                int r0 = n_off + ni * 8 + lr;
                bb[ni][0] = f2tf(Bs[buf][r0][k0 + lc]);
                bb[ni][1] = f2tf(Bs[buf][r0][k0 + lc + 4]);
            }
#pragma unroll
            for (int mi = 0; mi < 2; mi++)
#pragma unroll
                for (int ni = 0; ni < 4; ni++) {
                    MMA_TF32(c[mi][ni][0], c[mi][ni][1], c[mi][ni][2], c[mi][ni][3],
                             a[mi][0], a[mi][1], a[mi][2], a[mi][3],
                             bb[ni][0], bb[ni][1]);
                }
        }
        __syncthreads();
        buf ^= 1;
    }

    // epilogue: + bias, write fp32
    const int row_base = bm * BM + m_off;
    const int col_base = bn * BN + n_off;
#pragma unroll
    for (int mi = 0; mi < 2; mi++) {
#pragma unroll
        for (int ni = 0; ni < 4; ni++) {
            int r0 = row_base + mi * 16 + lr;
            int col = col_base + ni * 8 + 2 * lc;
            float b0 = bias[col], b1 = bias[col + 1];
            float2 v0 = make_float2(c[mi][ni][0] + b0, c[mi][ni][1] + b1);
            float2 v1 = make_float2(c[mi][ni][2] + b0, c[mi][ni][3] + b1);
            *reinterpret_cast<float2*>(out + (size_t)r0 * OUTc + col) = v0;
            *reinterpret_cast<float2*>(out + (size_t)(r0 + 8) * OUTc + col) = v1;
        }
    }
}

// ---------------- launcher -------------------------------------------------
extern "C" void kernel_launch(void* const* d_in, const int* in_sizes, int n_in,
                              void* d_out, int out_size) {
    const float* rep     = (const float*)d_in[0];
    const int*   ids     = (const int*)d_in[1];
    const int*   aa_len  = (const int*)d_in[2];
    const int*   seq_len = (const int*)d_in[3];
    const float* Wm      = (const float*)d_in[4];
    const float* bias    = (const float*)d_in[5];
    float*       out     = (float*)d_out;

    zero_kernel<<<(Bc * Dc + 255) / 256, 256>>>();
    pool_kernel<<<Bc * Sc, 128>>>(rep, ids, aa_len, seq_len);
    avg_kernel<<<Bc * (Sc / SCH), 128>>>();
    fill_kernel<<<Bc * Sc, 128>>>(seq_len);
    dim3 grid(Bc * Sc / BM, OUTc / BN);
    gemm_kernel<<<grid, GEMM_THREADS>>>(Wm, bias, out);
}

// round 3
// speedup vs baseline: 1.2245x; 1.2245x over previous
#include <cuda_runtime.h>
#include <cstdint>

// Problem shape (fixed by the dataset)
#define Bc   8
#define Ac   16384
#define Sc   2048
#define Dc   512
#define OUTc 512
#define CH   16      // residues per pool block

// ---------------- scratch (device globals; no allocation allowed) ----------
__device__ float g_pooled[Bc * Sc * Dc];   // 32 MB pooled [B,S,D], tf32-rounded
__device__ float g_Wtf[OUTc * Dc];         // W pre-rounded to tf32
__device__ float g_avgsum[Bc * Dc];        // per-protein sum over filled residues
__device__ int   g_filled[Bc * Sc];
__device__ int   g_nfill[Bc];

// ---------------- helpers --------------------------------------------------
__device__ __forceinline__ float f2tf_f(float x) {
    uint32_t r;
    asm("cvt.rna.tf32.f32 %0, %1;" : "=r"(r) : "f"(x));
    return __uint_as_float(r);
}

#define MMA_TF32(c0, c1, c2, c3, a0, a1, a2, a3, b0, b1)                      \
    asm volatile(                                                             \
        "mma.sync.aligned.m16n8k8.row.col.f32.tf32.tf32.f32 "                 \
        "{%0,%1,%2,%3}, {%4,%5,%6,%7}, {%8,%9}, {%0,%1,%2,%3};"               \
        : "+f"(c0), "+f"(c1), "+f"(c2), "+f"(c3)                              \
        : "r"(a0), "r"(a1), "r"(a2), "r"(a3), "r"(b0), "r"(b1))

__device__ __forceinline__ void cp_async16(void* smem_dst, const void* gmem_src) {
    uint32_t dst = (uint32_t)__cvta_generic_to_shared(smem_dst);
    asm volatile("cp.async.ca.shared.global [%0], [%1], 16;" ::"r"(dst), "l"(gmem_src));
}

// ---------------- kernel 0: zero accumulators + convert W to tf32 ----------
__global__ void prep_kernel(const float* __restrict__ W) {
    int i = blockIdx.x * 256 + threadIdx.x;
    if (i < OUTc * Dc) g_Wtf[i] = f2tf_f(W[i]);
    if (i < Bc * Dc) g_avgsum[i] = 0.0f;
    if (i < Bc) g_nfill[i] = 0;
}

// ---------------- kernel 1: fused segment-mean pooling + avg accumulation --
// One block per (b, chunk of CH residues). Atoms sorted by residue id.
__global__ void pool_kernel(const float* __restrict__ rep,
                            const int* __restrict__ ids,
                            const int* __restrict__ aa_len,
                            const int* __restrict__ seq_len) {
    const int blk = blockIdx.x;
    const int b = blk / (Sc / CH);
    const int s0 = (blk % (Sc / CH)) * CH;
    const int L = aa_len[b];
    const int SL = seq_len[b];
    const int* p = ids + b * Ac;

    __shared__ int bound[CH + 1];
    const int t = threadIdx.x;  // 128 threads x float4 = 512 cols

    if (t <= CH) {
        int target = s0 + t;
        int lo = 0, hi = L;
        while (lo < hi) { int mid = (lo + hi) >> 1; if (p[mid] < target) lo = mid + 1; else hi = mid; }
        bound[t] = lo;
    }
    __syncthreads();

    const float4* base = reinterpret_cast<const float4*>(rep) + (size_t)b * Ac * (Dc / 4);
    float4 avg = make_float4(0.f, 0.f, 0.f, 0.f);
    int nf_local = 0;

#pragma unroll 1
    for (int i = 0; i < CH; i++) {
        const int st = bound[i], en = bound[i + 1];
        float4 acc = make_float4(0.f, 0.f, 0.f, 0.f);
        int a = st;
        for (; a + 1 < en; a += 2) {
            float4 v0 = base[(size_t)a * (Dc / 4) + t];
            float4 v1 = base[(size_t)(a + 1) * (Dc / 4) + t];
            acc.x += v0.x + v1.x; acc.y += v0.y + v1.y;
            acc.z += v0.z + v1.z; acc.w += v0.w + v1.w;
        }
        if (a < en) {
            float4 v0 = base[(size_t)a * (Dc / 4) + t];
            acc.x += v0.x; acc.y += v0.y; acc.z += v0.z; acc.w += v0.w;
        }
        const int cnt = en - st;
        const float inv = 1.0f / (float)(cnt > 0 ? cnt : 1);
        acc.x = f2tf_f(acc.x * inv); acc.y = f2tf_f(acc.y * inv);
        acc.z = f2tf_f(acc.z * inv); acc.w = f2tf_f(acc.w * inv);

        const int row = b * Sc + s0 + i;
        reinterpret_cast<float4*>(g_pooled)[(size_t)row * (Dc / 4) + t] = acc;

        const bool fill = (cnt > 0) && (s0 + i < SL);
        if (fill) {
            avg.x += acc.x; avg.y += acc.y; avg.z += acc.z; avg.w += acc.w;
            nf_local++;
        }
        if (t == 0) g_filled[row] = fill ? 1 : 0;
    }

    atomicAdd(&g_avgsum[b * Dc + t * 4 + 0], avg.x);
    atomicAdd(&g_avgsum[b * Dc + t * 4 + 1], avg.y);
    atomicAdd(&g_avgsum[b * Dc + t * 4 + 2], avg.z);
    atomicAdd(&g_avgsum[b * Dc + t * 4 + 3], avg.w);
    if (t == 0) atomicAdd(&g_nfill[b], nf_local);
}

// ---------------- kernel 2: fill unfilled in-range rows with protein avg ---
// 128 blocks x 128 threads; fills are rare (~E[e^-8 * S] per protein).
__global__ void fill_kernel(const int* __restrict__ seq_len) {
    __shared__ int rows[128];
    __shared__ int nr;
    const int t = threadIdx.x;
    if (t == 0) nr = 0;
    __syncthreads();

    const int r = blockIdx.x * 128 + t;
    const int b = r / Sc, s = r % Sc;
    if (!g_filled[r] && s < seq_len[b]) rows[atomicAdd(&nr, 1)] = r;
    __syncthreads();

    for (int i = 0; i < nr; i++) {
        const int rr = rows[i];
        const int bb = rr / Sc;
        const int nf = g_nfill[bb];
        const float inv = 1.0f / (float)(nf > 0 ? nf : 1);
        float4 v;
        v.x = f2tf_f(g_avgsum[bb * Dc + t * 4 + 0] * inv);
        v.y = f2tf_f(g_avgsum[bb * Dc + t * 4 + 1] * inv);
        v.z = f2tf_f(g_avgsum[bb * Dc + t * 4 + 2] * inv);
        v.w = f2tf_f(g_avgsum[bb * Dc + t * 4 + 3] * inv);
        reinterpret_cast<float4*>(g_pooled)[(size_t)rr * (Dc / 4) + t] = v;
    }
}

// ---------------- kernel 3: GEMM out = pooled @ W^T + bias (tf32 mma) ------
// M = 16384, N = 512, K = 512. BM=128, BN=128, BK=16, 3-stage cp.async.
#define BM 128
#define BN 128
#define BK 16
#define PADK 20     // BK + 4 floats: conflict-free for both frag loads & stores
#define STG 3
#define GEMM_THREADS 256
#define SMEM_BYTES (STG * (BM + BN) * PADK * 4)

__global__ __launch_bounds__(GEMM_THREADS)
void gemm_kernel(const float* __restrict__ bias, float* __restrict__ out) {
    extern __shared__ float smem[];
    float* AsBase = smem;                         // [STG][BM][PADK]
    float* BsBase = smem + STG * BM * PADK;       // [STG][BN][PADK]

    const int tid = threadIdx.x;
    const int bm = blockIdx.x, bn = blockIdx.y;

    const float* Aori = g_pooled + (size_t)bm * BM * Dc;
    const float* Bori = g_Wtf + (size_t)bn * BN * Dc;

    const int warp = tid >> 5, lane = tid & 31;
    const int wm = warp >> 2, wn = warp & 3;      // 2 x 4 warp grid
    const int m_off = wm * 64, n_off = wn * 32;   // 64x32 warp tile
    const int lr = lane >> 2, lc = lane & 3;

    float c[4][4][4];
#pragma unroll
    for (int mi = 0; mi < 4; mi++)
#pragma unroll
        for (int ni = 0; ni < 4; ni++)
#pragma unroll
            for (int j = 0; j < 4; j++) c[mi][ni][j] = 0.f;

    // per-thread load coords (A: 512 float4 chunks, B: 512 float4 chunks)
    auto load_tile = [&](int kt, int st) {
        const int k0 = kt * BK;
        float* A = AsBase + st * BM * PADK;
        float* B = BsBase + st * BN * PADK;
#pragma unroll
        for (int i = 0; i < 2; i++) {
            int idx = tid + i * 256;
            int row = idx >> 2, c4 = idx & 3;
            cp_async16(A + row * PADK + c4 * 4, Aori + row * Dc + k0 + c4 * 4);
        }
#pragma unroll
        for (int i = 0; i < 2; i++) {
            int idx = tid + i * 256;
            int row = idx >> 2, c4 = idx & 3;
            cp_async16(B + row * PADK + c4 * 4, Bori + row * Dc + k0 + c4 * 4);
        }
    };

    const int KT = Dc / BK;  // 32
    load_tile(0, 0);
    asm volatile("cp.async.commit_group;");
    load_tile(1, 1);
    asm volatile("cp.async.commit_group;");

    for (int kt = 0; kt < KT; kt++) {
        asm volatile("cp.async.wait_group 1;");
        __syncthreads();
        if (kt + 2 < KT) load_tile(kt + 2, (kt + 2) % STG);
        asm volatile("cp.async.commit_group;");

        const float* A = AsBase + (kt % STG) * BM * PADK;
        const float* B = BsBase + (kt % STG) * BN * PADK;

#pragma unroll
        for (int ks = 0; ks < 2; ks++) {
            const int k0 = ks * 8;
            float a[4][4], bb[4][2];
#pragma unroll
            for (int mi = 0; mi < 4; mi++) {
                const float* Ar = A + (m_off + mi * 16 + lr) * PADK + k0 + lc;
                a[mi][0] = Ar[0];
                a[mi][1] = Ar[8 * PADK];
                a[mi][2] = Ar[4];
                a[mi][3] = Ar[8 * PADK + 4];
            }
#pragma unroll
            for (int ni = 0; ni < 4; ni++) {
                const float* Br = B + (n_off + ni * 8 + lr) * PADK + k0 + lc;
                bb[ni][0] = Br[0];
                bb[ni][1] = Br[4];
            }
#pragma unroll
            for (int mi = 0; mi < 4; mi++)
#pragma unroll
                for (int ni = 0; ni < 4; ni++) {
                    MMA_TF32(c[mi][ni][0], c[mi][ni][1], c[mi][ni][2], c[mi][ni][3],
                             __float_as_uint(a[mi][0]), __float_as_uint(a[mi][1]),
                             __float_as_uint(a[mi][2]), __float_as_uint(a[mi][3]),
                             __float_as_uint(bb[ni][0]), __float_as_uint(bb[ni][1]));
                }
        }
    }

    // epilogue: + bias, write fp32
    const int row_base = bm * BM + m_off;
    const int col_base = bn * BN + n_off;
#pragma unroll
    for (int mi = 0; mi < 4; mi++) {
#pragma unroll
        for (int ni = 0; ni < 4; ni++) {
            int r0 = row_base + mi * 16 + lr;
            int col = col_base + ni * 8 + 2 * lc;
            float b0 = bias[col], b1 = bias[col + 1];
            float2 v0 = make_float2(c[mi][ni][0] + b0, c[mi][ni][1] + b1);
            float2 v1 = make_float2(c[mi][ni][2] + b0, c[mi][ni][3] + b1);
            *reinterpret_cast<float2*>(out + (size_t)r0 * OUTc + col) = v0;
            *reinterpret_cast<float2*>(out + (size_t)(r0 + 8) * OUTc + col) = v1;
        }
    }
}

// ---------------- launcher -------------------------------------------------
extern "C" void kernel_launch(void* const* d_in, const int* in_sizes, int n_in,
                              void* d_out, int out_size) {
    const float* rep     = (const float*)d_in[0];
    const int*   ids     = (const int*)d_in[1];
    const int*   aa_len  = (const int*)d_in[2];
    const int*   seq_len = (const int*)d_in[3];
    const float* Wm      = (const float*)d_in[4];
    const float* bias    = (const float*)d_in[5];
    float*       out     = (float*)d_out;

    static bool attr_done = false;
    if (!attr_done) {
        cudaFuncSetAttribute(gemm_kernel, cudaFuncAttributeMaxDynamicSharedMemorySize,
                             SMEM_BYTES);
        attr_done = true;
    }

    prep_kernel<<<(OUTc * Dc + 255) / 256, 256>>>(Wm);
    pool_kernel<<<Bc * (Sc / CH), 128>>>(rep, ids, aa_len, seq_len);
    fill_kernel<<<Bc * Sc / 128, 128>>>(seq_len);
    dim3 grid(Bc * Sc / BM, OUTc / BN);
    gemm_kernel<<<grid, GEMM_THREADS, SMEM_BYTES>>>(bias, out);
}

// round 5
// speedup vs baseline: 1.2588x; 1.0280x over previous
#include <cuda_runtime.h>
#include <cstdint>

// Problem shape (fixed by the dataset)
#define Bc   8
#define Ac   16384
#define Sc   2048
#define Dc   512
#define OUTc 512
#define CH   16      // residues per pool block

// K-dimension permutation (within each 8-col group): old col c -> position
//   p(c) = (c & ~7) | ((c & 3) << 1) | ((c >> 2) & 1)
// so old pair (lc, lc+4) lands at adjacent positions (2lc, 2lc+1) -> LDS.64 frags.
__host__ __device__ __forceinline__ int kperm(int c) {
    return (c & ~7) | (((c & 3) << 1) | ((c >> 2) & 1));
}

// ---------------- scratch (device globals; no allocation allowed) ----------
__device__ float g_pooled[Bc * Sc * Dc];   // 32 MB pooled [B,S,D], tf32, k-permuted
__device__ float g_Wtf[OUTc * Dc];         // W tf32-rounded, k-permuted
__device__ float g_avgsum[Bc * Dc];        // per-protein sums (k-permuted space)
__device__ int   g_filled[Bc * Sc];
__device__ int   g_nfill[Bc];

// ---------------- helpers --------------------------------------------------
__device__ __forceinline__ float f2tf_f(float x) {
    uint32_t r;
    asm("cvt.rna.tf32.f32 %0, %1;" : "=r"(r) : "f"(x));
    return __uint_as_float(r);
}

#define MMA_TF32(c0, c1, c2, c3, a0, a1, a2, a3, b0, b1)                      \
    asm volatile(                                                             \
        "mma.sync.aligned.m16n8k8.row.col.f32.tf32.tf32.f32 "                 \
        "{%0,%1,%2,%3}, {%4,%5,%6,%7}, {%8,%9}, {%0,%1,%2,%3};"               \
        : "+f"(c0), "+f"(c1), "+f"(c2), "+f"(c3)                              \
        : "r"(a0), "r"(a1), "r"(a2), "r"(a3), "r"(b0), "r"(b1))

__device__ __forceinline__ void cp_async16(void* smem_dst, const void* gmem_src) {
    uint32_t dst = (uint32_t)__cvta_generic_to_shared(smem_dst);
    asm volatile("cp.async.ca.shared.global [%0], [%1], 16;" ::"r"(dst), "l"(gmem_src));
}

// ---------------- kernel 0: zero accumulators + convert W to tf32 ----------
__global__ void prep_kernel(const float* __restrict__ W) {
    int i = blockIdx.x * 256 + threadIdx.x;
    if (i < OUTc * Dc) {
        int o = i >> 9, k = i & 511;
        g_Wtf[(o << 9) + kperm(k)] = f2tf_f(W[i]);
    }
    if (i < Bc * Dc) g_avgsum[i] = 0.0f;
    if (i < Bc) g_nfill[i] = 0;
}

// ---------------- kernel 1: fused segment-mean pooling + avg accumulation --
__global__ void pool_kernel(const float* __restrict__ rep,
                            const int* __restrict__ ids,
                            const int* __restrict__ aa_len,
                            const int* __restrict__ seq_len) {
    const int blk = blockIdx.x;
    const int b = blk / (Sc / CH);
    const int s0 = (blk % (Sc / CH)) * CH;
    const int L = aa_len[b];
    const int SL = seq_len[b];
    const int* p = ids + b * Ac;

    __shared__ int bound[CH + 1];
    const int t = threadIdx.x;  // 128 threads x 4 cols = 512 cols

    if (t <= CH) {
        int target = s0 + t;
        int lo = 0, hi = L;
        while (lo < hi) { int mid = (lo + hi) >> 1; if (p[mid] < target) lo = mid + 1; else hi = mid; }
        bound[t] = lo;
    }
    __syncthreads();

    // permuted destination columns for this thread's old cols 4t..4t+3
    const int nc0 = kperm(4 * t + 0), nc1 = kperm(4 * t + 1);
    const int nc2 = kperm(4 * t + 2), nc3 = kperm(4 * t + 3);

    const float4* base = reinterpret_cast<const float4*>(rep) + (size_t)b * Ac * (Dc / 4);
    float4 avg = make_float4(0.f, 0.f, 0.f, 0.f);
    int nf_local = 0;

#pragma unroll 1
    for (int i = 0; i < CH; i++) {
        const int st = bound[i], en = bound[i + 1];
        float4 acc = make_float4(0.f, 0.f, 0.f, 0.f);
        int a = st;
        for (; a + 1 < en; a += 2) {
            float4 v0 = base[(size_t)a * (Dc / 4) + t];
            float4 v1 = base[(size_t)(a + 1) * (Dc / 4) + t];
            acc.x += v0.x + v1.x; acc.y += v0.y + v1.y;
            acc.z += v0.z + v1.z; acc.w += v0.w + v1.w;
        }
        if (a < en) {
            float4 v0 = base[(size_t)a * (Dc / 4) + t];
            acc.x += v0.x; acc.y += v0.y; acc.z += v0.z; acc.w += v0.w;
        }
        const int cnt = en - st;
        const float inv = 1.0f / (float)(cnt > 0 ? cnt : 1);
        acc.x = f2tf_f(acc.x * inv); acc.y = f2tf_f(acc.y * inv);
        acc.z = f2tf_f(acc.z * inv); acc.w = f2tf_f(acc.w * inv);

        const int row = b * Sc + s0 + i;
        float* pr = g_pooled + (size_t)row * Dc;
        pr[nc0] = acc.x; pr[nc1] = acc.y; pr[nc2] = acc.z; pr[nc3] = acc.w;

        const bool fill = (cnt > 0) && (s0 + i < SL);
        if (fill) {
            avg.x += acc.x; avg.y += acc.y; avg.z += acc.z; avg.w += acc.w;
            nf_local++;
        }
        if (t == 0) g_filled[row] = fill ? 1 : 0;
    }

    atomicAdd(&g_avgsum[b * Dc + nc0], avg.x);
    atomicAdd(&g_avgsum[b * Dc + nc1], avg.y);
    atomicAdd(&g_avgsum[b * Dc + nc2], avg.z);
    atomicAdd(&g_avgsum[b * Dc + nc3], avg.w);
    if (t == 0) atomicAdd(&g_nfill[b], nf_local);
}

// ---------------- kernel 2: fill unfilled in-range rows with protein avg ---
// avgsum and pooled are both in permuted space -> linear float4 copy is fine.
__global__ void fill_kernel(const int* __restrict__ seq_len) {
    __shared__ int rows[128];
    __shared__ int nr;
    const int t = threadIdx.x;
    if (t == 0) nr = 0;
    __syncthreads();

    const int r = blockIdx.x * 128 + t;
    const int b = r / Sc, s = r % Sc;
    if (!g_filled[r] && s < seq_len[b]) rows[atomicAdd(&nr, 1)] = r;
    __syncthreads();

    for (int i = 0; i < nr; i++) {
        const int rr = rows[i];
        const int bb = rr / Sc;
        const int nf = g_nfill[bb];
        const float inv = 1.0f / (float)(nf > 0 ? nf : 1);
        float4 v;
        v.x = f2tf_f(g_avgsum[bb * Dc + t * 4 + 0] * inv);
        v.y = f2tf_f(g_avgsum[bb * Dc + t * 4 + 1] * inv);
        v.z = f2tf_f(g_avgsum[bb * Dc + t * 4 + 2] * inv);
        v.w = f2tf_f(g_avgsum[bb * Dc + t * 4 + 3] * inv);
        reinterpret_cast<float4*>(g_pooled)[(size_t)rr * (Dc / 4) + t] = v;
    }
}

// ---------------- kernel 3: GEMM out = pooled @ W^T + bias (tf32 mma) ------
// M=16384, N=512, K=512. BM=BN=128, BK=16, 3-stage cp.async.
// 4 warps (128 thr), warp tile 64x64. Fragments via LDS.64 (k-permuted data).
#define BM 128
#define BN 128
#define BK 16
#define PADK 24     // conflict-free for LDS.64 fragment reads (verified per-phase)
#define STG 3
#define GEMM_THREADS 128
#define SMEM_BYTES (STG * (BM + BN) * PADK * 4)

__global__ __launch_bounds__(GEMM_THREADS)
void gemm_kernel(const float* __restrict__ bias, float* __restrict__ out) {
    extern __shared__ float smem[];
    float* AsBase = smem;                         // [STG][BM][PADK]
    float* BsBase = smem + STG * BM * PADK;       // [STG][BN][PADK]

    const int tid = threadIdx.x;
    const int bm = blockIdx.x, bn = blockIdx.y;

    const float* Aori = g_pooled + (size_t)bm * BM * Dc;
    const float* Bori = g_Wtf + (size_t)bn * BN * Dc;

    const int warp = tid >> 5, lane = tid & 31;
    const int wm = warp >> 1, wn = warp & 1;      // 2 x 2 warp grid
    const int m_off = wm * 64, n_off = wn * 64;   // 64x64 warp tile
    const int lr = lane >> 2, lc = lane & 3;

    float c[4][8][4];
#pragma unroll
    for (int mi = 0; mi < 4; mi++)
#pragma unroll
        for (int ni = 0; ni < 8; ni++)
#pragma unroll
            for (int j = 0; j < 4; j++) c[mi][ni][j] = 0.f;

    // A: 128 rows x 16 cols = 512 x 16B chunks; 128 threads -> 4 each. B same.
    auto load_tile = [&](int kt, int st) {
        const int k0 = kt * BK;
        float* A = AsBase + st * BM * PADK;
        float* B = BsBase + st * BN * PADK;
#pragma unroll
        for (int i = 0; i < 4; i++) {
            int idx = tid + i * 128;
            int row = idx >> 2, c4 = idx & 3;
            cp_async16(A + row * PADK + c4 * 4, Aori + (size_t)row * Dc + k0 + c4 * 4);
        }
#pragma unroll
        for (int i = 0; i < 4; i++) {
            int idx = tid + i * 128;
            int row = idx >> 2, c4 = idx & 3;
            cp_async16(B + row * PADK + c4 * 4, Bori + (size_t)row * Dc + k0 + c4 * 4);
        }
        asm volatile("cp.async.commit_group;");
    };

    const int KT = Dc / BK;  // 32
    load_tile(0, 0);
    load_tile(1, 1);

    for (int kt = 0; kt < KT; kt++) {
        asm volatile("cp.async.wait_group 1;");
        __syncthreads();
        if (kt + 2 < KT) load_tile(kt + 2, (kt + 2) % STG);

        const float* A = AsBase + (kt % STG) * BM * PADK;
        const float* B = BsBase + (kt % STG) * BN * PADK;

#pragma unroll
        for (int ks = 0; ks < 2; ks++) {
            const int k0 = ks * 8 + 2 * lc;
            float2 alo[4], ahi[4], bv[8];
#pragma unroll
            for (int mi = 0; mi < 4; mi++) {
                const int r0 = m_off + mi * 16 + lr;
                alo[mi] = *reinterpret_cast<const float2*>(A + r0 * PADK + k0);
                ahi[mi] = *reinterpret_cast<const float2*>(A + (r0 + 8) * PADK + k0);
            }
#pragma unroll
            for (int ni = 0; ni < 8; ni++) {
                const int r0 = n_off + ni * 8 + lr;
                bv[ni] = *reinterpret_cast<const float2*>(B + r0 * PADK + k0);
            }
#pragma unroll
            for (int mi = 0; mi < 4; mi++)
#pragma unroll
                for (int ni = 0; ni < 8; ni++) {
                    MMA_TF32(c[mi][ni][0], c[mi][ni][1], c[mi][ni][2], c[mi][ni][3],
                             __float_as_uint(alo[mi].x), __float_as_uint(ahi[mi].x),
                             __float_as_uint(alo[mi].y), __float_as_uint(ahi[mi].y),
                             __float_as_uint(bv[ni].x), __float_as_uint(bv[ni].y));
                }
        }
        __syncthreads();
    }

    // epilogue: + bias, write fp32
    const int row_base = bm * BM + m_off;
    const int col_base = bn * BN + n_off;
#pragma unroll
    for (int mi = 0; mi < 4; mi++) {
#pragma unroll
        for (int ni = 0; ni < 8; ni++) {
            int r0 = row_base + mi * 16 + lr;
            int col = col_base + ni * 8 + 2 * lc;
            float b0 = bias[col], b1 = bias[col + 1];
            float2 v0 = make_float2(c[mi][ni][0] + b0, c[mi][ni][1] + b1);
            float2 v1 = make_float2(c[mi][ni][2] + b0, c[mi][ni][3] + b1);
            *reinterpret_cast<float2*>(out + (size_t)r0 * OUTc + col) = v0;
            *reinterpret_cast<float2*>(out + (size_t)(r0 + 8) * OUTc + col) = v1;
        }
    }
}

// ---------------- launcher -------------------------------------------------
extern "C" void kernel_launch(void* const* d_in, const int* in_sizes, int n_in,
                              void* d_out, int out_size) {
    const float* rep     = (const float*)d_in[0];
    const int*   ids     = (const int*)d_in[1];
    const int*   aa_len  = (const int*)d_in[2];
    const int*   seq_len = (const int*)d_in[3];
    const float* Wm      = (const float*)d_in[4];
    const float* bias    = (const float*)d_in[5];
    float*       out     = (float*)d_out;

    static bool attr_done = false;
    if (!attr_done) {
        cudaFuncSetAttribute(gemm_kernel, cudaFuncAttributeMaxDynamicSharedMemorySize,
                             SMEM_BYTES);
        attr_done = true;
    }

    prep_kernel<<<(OUTc * Dc + 255) / 256, 256>>>(Wm);
    pool_kernel<<<Bc * (Sc / CH), 128>>>(rep, ids, aa_len, seq_len);
    fill_kernel<<<Bc * Sc / 128, 128>>>(seq_len);
    dim3 grid(Bc * Sc / BM, OUTc / BN);
    gemm_kernel<<<grid, GEMM_THREADS, SMEM_BYTES>>>(bias, out);
}

// round 6
// speedup vs baseline: 1.3381x; 1.0629x over previous
#include <cuda_runtime.h>
#include <cstdint>

// Problem shape (fixed by the dataset)
#define Bc   8
#define Ac   16384
#define Sc   2048
#define Dc   512
#define OUTc 512
#define CH   16      // residues per pool block

// K-dimension permutation (within each 8-col group): old col c -> position
//   p(c) = (c & ~7) | ((c & 3) << 1) | ((c >> 2) & 1)
// so old pair (lc, lc+4) lands at adjacent positions (2lc, 2lc+1) -> LDS.64 frags.
__host__ __device__ __forceinline__ int kperm(int c) {
    return (c & ~7) | (((c & 3) << 1) | ((c >> 2) & 1));
}

// ---------------- scratch (device globals; no allocation allowed) ----------
__device__ float g_pooled[Bc * Sc * Dc];   // 32 MB pooled [B,S,D], tf32, k-permuted
__device__ float g_Wtf[OUTc * Dc];         // W tf32-rounded, k-permuted
__device__ float g_avgsum[Bc * Dc];        // per-protein sums (k-permuted space)
__device__ int   g_filled[Bc * Sc];
__device__ int   g_nfill[Bc];

// ---------------- helpers --------------------------------------------------
__device__ __forceinline__ float f2tf_f(float x) {
    uint32_t r;
    asm("cvt.rna.tf32.f32 %0, %1;" : "=r"(r) : "f"(x));
    return __uint_as_float(r);
}

#define MMA_TF32(c0, c1, c2, c3, a0, a1, a2, a3, b0, b1)                      \
    asm volatile(                                                             \
        "mma.sync.aligned.m16n8k8.row.col.f32.tf32.tf32.f32 "                 \
        "{%0,%1,%2,%3}, {%4,%5,%6,%7}, {%8,%9}, {%0,%1,%2,%3};"               \
        : "+f"(c0), "+f"(c1), "+f"(c2), "+f"(c3)                              \
        : "r"(a0), "r"(a1), "r"(a2), "r"(a3), "r"(b0), "r"(b1))

__device__ __forceinline__ void cp_async16cg(void* smem_dst, const void* gmem_src) {
    uint32_t dst = (uint32_t)__cvta_generic_to_shared(smem_dst);
    asm volatile("cp.async.cg.shared.global [%0], [%1], 16;" ::"r"(dst), "l"(gmem_src));
}

// ---------------- kernel 0: zero accumulators + convert W to tf32 ----------
__global__ void prep_kernel(const float* __restrict__ W) {
    int i = blockIdx.x * 256 + threadIdx.x;
    if (i < OUTc * Dc) {
        int o = i >> 9, k = i & 511;
        g_Wtf[(o << 9) + kperm(k)] = f2tf_f(W[i]);
    }
    if (i < Bc * Dc) g_avgsum[i] = 0.0f;
    if (i < Bc) g_nfill[i] = 0;
}

// ---------------- kernel 1: fused segment-mean pooling + avg accumulation --
__global__ void pool_kernel(const float* __restrict__ rep,
                            const int* __restrict__ ids,
                            const int* __restrict__ aa_len,
                            const int* __restrict__ seq_len) {
    const int blk = blockIdx.x;
    const int b = blk / (Sc / CH);
    const int s0 = (blk % (Sc / CH)) * CH;
    const int L = aa_len[b];
    const int SL = seq_len[b];
    const int* p = ids + b * Ac;

    __shared__ int bound[CH + 1];
    const int t = threadIdx.x;  // 128 threads x 4 cols = 512 cols

    if (t <= CH) {
        int target = s0 + t;
        int lo = 0, hi = L;
        while (lo < hi) { int mid = (lo + hi) >> 1; if (p[mid] < target) lo = mid + 1; else hi = mid; }
        bound[t] = lo;
    }
    __syncthreads();

    // permuted destination columns for this thread's old cols 4t..4t+3
    const int nc0 = kperm(4 * t + 0), nc1 = kperm(4 * t + 1);
    const int nc2 = kperm(4 * t + 2), nc3 = kperm(4 * t + 3);

    const float4* base = reinterpret_cast<const float4*>(rep) + (size_t)b * Ac * (Dc / 4);
    float4 avg = make_float4(0.f, 0.f, 0.f, 0.f);
    int nf_local = 0;

#pragma unroll 1
    for (int i = 0; i < CH; i++) {
        const int st = bound[i], en = bound[i + 1];
        float4 acc = make_float4(0.f, 0.f, 0.f, 0.f);
        int a = st;
        for (; a + 1 < en; a += 2) {
            float4 v0 = base[(size_t)a * (Dc / 4) + t];
            float4 v1 = base[(size_t)(a + 1) * (Dc / 4) + t];
            acc.x += v0.x + v1.x; acc.y += v0.y + v1.y;
            acc.z += v0.z + v1.z; acc.w += v0.w + v1.w;
        }
        if (a < en) {
            float4 v0 = base[(size_t)a * (Dc / 4) + t];
            acc.x += v0.x; acc.y += v0.y; acc.z += v0.z; acc.w += v0.w;
        }
        const int cnt = en - st;
        const float inv = 1.0f / (float)(cnt > 0 ? cnt : 1);
        acc.x = f2tf_f(acc.x * inv); acc.y = f2tf_f(acc.y * inv);
        acc.z = f2tf_f(acc.z * inv); acc.w = f2tf_f(acc.w * inv);

        const int row = b * Sc + s0 + i;
        float* pr = g_pooled + (size_t)row * Dc;
        pr[nc0] = acc.x; pr[nc1] = acc.y; pr[nc2] = acc.z; pr[nc3] = acc.w;

        const bool fill = (cnt > 0) && (s0 + i < SL);
        if (fill) {
            avg.x += acc.x; avg.y += acc.y; avg.z += acc.z; avg.w += acc.w;
            nf_local++;
        }
        if (t == 0) g_filled[row] = fill ? 1 : 0;
    }

    atomicAdd(&g_avgsum[b * Dc + nc0], avg.x);
    atomicAdd(&g_avgsum[b * Dc + nc1], avg.y);
    atomicAdd(&g_avgsum[b * Dc + nc2], avg.z);
    atomicAdd(&g_avgsum[b * Dc + nc3], avg.w);
    if (t == 0) atomicAdd(&g_nfill[b], nf_local);
}

// ---------------- kernel 2: fill unfilled in-range rows with protein avg ---
// avgsum and pooled are both in permuted space -> linear float4 copy is fine.
__global__ void fill_kernel(const int* __restrict__ seq_len) {
    __shared__ int rows[128];
    __shared__ int nr;
    const int t = threadIdx.x;
    if (t == 0) nr = 0;
    __syncthreads();

    const int r = blockIdx.x * 128 + t;
    const int b = r / Sc, s = r % Sc;
    if (!g_filled[r] && s < seq_len[b]) rows[atomicAdd(&nr, 1)] = r;
    __syncthreads();

    for (int i = 0; i < nr; i++) {
        const int rr = rows[i];
        const int bb = rr / Sc;
        const int nf = g_nfill[bb];
        const float inv = 1.0f / (float)(nf > 0 ? nf : 1);
        float4 v;
        v.x = f2tf_f(g_avgsum[bb * Dc + t * 4 + 0] * inv);
        v.y = f2tf_f(g_avgsum[bb * Dc + t * 4 + 1] * inv);
        v.z = f2tf_f(g_avgsum[bb * Dc + t * 4 + 2] * inv);
        v.w = f2tf_f(g_avgsum[bb * Dc + t * 4 + 3] * inv);
        reinterpret_cast<float4*>(g_pooled)[(size_t)rr * (Dc / 4) + t] = v;
    }
}

// ---------------- kernel 3: GEMM out = pooled @ W^T + bias (tf32 mma) ------
// M=16384, N=512, K=512. BM=BN=128, BK=16, 3-stage cp.async, ONE sync/iter.
// 8 warps (256 thr), warp tile 64x32. Fragments via LDS.64 (k-permuted data).
#define BM 128
#define BN 128
#define BK 16
#define PADK 24     // conflict-free for LDS.64 fragment reads (verified per-phase)
#define STG 3
#define GEMM_THREADS 256
#define SMEM_BYTES (STG * (BM + BN) * PADK * 4)

__global__ __launch_bounds__(GEMM_THREADS)
void gemm_kernel(const float* __restrict__ bias, float* __restrict__ out) {
    extern __shared__ float smem[];
    float* AsBase = smem;                         // [STG][BM][PADK]
    float* BsBase = smem + STG * BM * PADK;       // [STG][BN][PADK]

    const int tid = threadIdx.x;
    const int bm = blockIdx.x, bn = blockIdx.y;

    const float* Aori = g_pooled + (size_t)bm * BM * Dc;
    const float* Bori = g_Wtf + (size_t)bn * BN * Dc;

    const int warp = tid >> 5, lane = tid & 31;
    const int wm = warp >> 2, wn = warp & 3;      // 2 x 4 warp grid
    const int m_off = wm * 64, n_off = wn * 32;   // 64x32 warp tile
    const int lr = lane >> 2, lc = lane & 3;

    float c[4][4][4];
#pragma unroll
    for (int mi = 0; mi < 4; mi++)
#pragma unroll
        for (int ni = 0; ni < 4; ni++)
#pragma unroll
            for (int j = 0; j < 4; j++) c[mi][ni][j] = 0.f;

    // A: 128 rows x 16 cols = 512 x 16B chunks; 256 threads -> 2 each. B same.
    auto load_tile = [&](int kt, int st) {
        const int k0 = kt * BK;
        float* A = AsBase + st * BM * PADK;
        float* B = BsBase + st * BN * PADK;
#pragma unroll
        for (int i = 0; i < 2; i++) {
            int idx = tid + i * 256;
            int row = idx >> 2, c4 = idx & 3;
            cp_async16cg(A + row * PADK + c4 * 4, Aori + (size_t)row * Dc + k0 + c4 * 4);
        }
#pragma unroll
        for (int i = 0; i < 2; i++) {
            int idx = tid + i * 256;
            int row = idx >> 2, c4 = idx & 3;
            cp_async16cg(B + row * PADK + c4 * 4, Bori + (size_t)row * Dc + k0 + c4 * 4);
        }
        asm volatile("cp.async.commit_group;");
    };

    const int KT = Dc / BK;  // 32
    load_tile(0, 0);
    load_tile(1, 1);

    for (int kt = 0; kt < KT; kt++) {
        asm volatile("cp.async.wait_group 1;");
        __syncthreads();
        if (kt + 2 < KT) load_tile(kt + 2, (kt + 2) % STG);

        const float* A = AsBase + (kt % STG) * BM * PADK;
        const float* B = BsBase + (kt % STG) * BN * PADK;

#pragma unroll
        for (int ks = 0; ks < 2; ks++) {
            const int k0 = ks * 8 + 2 * lc;
            float2 alo[4], ahi[4], bv[4];
#pragma unroll
            for (int mi = 0; mi < 4; mi++) {
                const int r0 = m_off + mi * 16 + lr;
                alo[mi] = *reinterpret_cast<const float2*>(A + r0 * PADK + k0);
                ahi[mi] = *reinterpret_cast<const float2*>(A + (r0 + 8) * PADK + k0);
            }
#pragma unroll
            for (int ni = 0; ni < 4; ni++) {
                const int r0 = n_off + ni * 8 + lr;
                bv[ni] = *reinterpret_cast<const float2*>(B + r0 * PADK + k0);
            }
#pragma unroll
            for (int mi = 0; mi < 4; mi++)
#pragma unroll
                for (int ni = 0; ni < 4; ni++) {
                    MMA_TF32(c[mi][ni][0], c[mi][ni][1], c[mi][ni][2], c[mi][ni][3],
                             __float_as_uint(alo[mi].x), __float_as_uint(ahi[mi].x),
                             __float_as_uint(alo[mi].y), __float_as_uint(ahi[mi].y),
                             __float_as_uint(bv[ni].x), __float_as_uint(bv[ni].y));
                }
        }
        // NOTE: no trailing sync — STG=3 guarantees the stage written by the
        // next iteration's load ((kt+3)%3) was fully consumed before the
        // top-of-loop barrier of iteration kt+1 releases.
    }

    // epilogue: + bias, write fp32
    const int row_base = bm * BM + m_off;
    const int col_base = bn * BN + n_off;
#pragma unroll
    for (int mi = 0; mi < 4; mi++) {
#pragma unroll
        for (int ni = 0; ni < 4; ni++) {
            int r0 = row_base + mi * 16 + lr;
            int col = col_base + ni * 8 + 2 * lc;
            float b0 = bias[col], b1 = bias[col + 1];
            float2 v0 = make_float2(c[mi][ni][0] + b0, c[mi][ni][1] + b1);
            float2 v1 = make_float2(c[mi][ni][2] + b0, c[mi][ni][3] + b1);
            *reinterpret_cast<float2*>(out + (size_t)r0 * OUTc + col) = v0;
            *reinterpret_cast<float2*>(out + (size_t)(r0 + 8) * OUTc + col) = v1;
        }
    }
}

// ---------------- launcher -------------------------------------------------
extern "C" void kernel_launch(void* const* d_in, const int* in_sizes, int n_in,
                              void* d_out, int out_size) {
    const float* rep     = (const float*)d_in[0];
    const int*   ids     = (const int*)d_in[1];
    const int*   aa_len  = (const int*)d_in[2];
    const int*   seq_len = (const int*)d_in[3];
    const float* Wm      = (const float*)d_in[4];
    const float* bias    = (const float*)d_in[5];
    float*       out     = (float*)d_out;

    static bool attr_done = false;
    if (!attr_done) {
        cudaFuncSetAttribute(gemm_kernel, cudaFuncAttributeMaxDynamicSharedMemorySize,
                             SMEM_BYTES);
        attr_done = true;
    }

    prep_kernel<<<(OUTc * Dc + 255) / 256, 256>>>(Wm);
    pool_kernel<<<Bc * (Sc / CH), 128>>>(rep, ids, aa_len, seq_len);
    fill_kernel<<<Bc * Sc / 128, 128>>>(seq_len);
    dim3 grid(Bc * Sc / BM, OUTc / BN);
    gemm_kernel<<<grid, GEMM_THREADS, SMEM_BYTES>>>(bias, out);
}

// round 10
// speedup vs baseline: 1.3910x; 1.0396x over previous
#include <cuda_runtime.h>
#include <cstdint>

// Problem shape (fixed by the dataset)
#define Bc   8
#define Ac   16384
#define Sc   2048
#define Dc   512
#define OUTc 512
#define CH   16      // residues per pool block

// K-dimension permutation (within each 8-col group): old col c -> position
//   p(c) = (c & ~7) | ((c & 3) << 1) | ((c >> 2) & 1)
// so old pair (lc, lc+4) lands at adjacent positions (2lc, 2lc+1) -> LDS.64 frags.
__host__ __device__ __forceinline__ int kperm(int c) {
    return (c & ~7) | (((c & 3) << 1) | ((c >> 2) & 1));
}

// ---------------- scratch (device globals; no allocation allowed) ----------
__device__ float g_pooled[Bc * Sc * Dc];   // 32 MB pooled [B,S,D], tf32, k-permuted
__device__ float g_Wtf[OUTc * Dc];         // W tf32-rounded, k-permuted
__device__ float g_avgsum[Bc * Dc];        // per-protein sums (k-permuted space)
__device__ int   g_filled[Bc * Sc];
__device__ int   g_nfill[Bc];

// ---------------- helpers --------------------------------------------------
__device__ __forceinline__ float f2tf_f(float x) {
    uint32_t r;
    asm("cvt.rna.tf32.f32 %0, %1;" : "=r"(r) : "f"(x));
    return __uint_as_float(r);
}

#define MMA_TF32(c0, c1, c2, c3, a0, a1, a2, a3, b0, b1)                      \
    asm volatile(                                                             \
        "mma.sync.aligned.m16n8k8.row.col.f32.tf32.tf32.f32 "                 \
        "{%0,%1,%2,%3}, {%4,%5,%6,%7}, {%8,%9}, {%0,%1,%2,%3};"               \
        : "+f"(c0), "+f"(c1), "+f"(c2), "+f"(c3)                              \
        : "r"(a0), "r"(a1), "r"(a2), "r"(a3), "r"(b0), "r"(b1))

__device__ __forceinline__ void cp_async16cg(void* smem_dst, const void* gmem_src) {
    uint32_t dst = (uint32_t)__cvta_generic_to_shared(smem_dst);
    asm volatile("cp.async.cg.shared.global [%0], [%1], 16;" ::"r"(dst), "l"(gmem_src));
}

// ---------------- kernel 0: zero accumulators + convert W to tf32 ----------
__global__ void prep_kernel(const float* __restrict__ W) {
    int i = blockIdx.x * 256 + threadIdx.x;
    if (i < OUTc * Dc) {
        int o = i >> 9, k = i & 511;
        g_Wtf[(o << 9) + kperm(k)] = f2tf_f(W[i]);
    }
    if (i < Bc * Dc) g_avgsum[i] = 0.0f;
    if (i < Bc) g_nfill[i] = 0;
}

// ---------------- kernel 1: fused segment-mean pooling + avg accumulation --
__global__ void pool_kernel(const float* __restrict__ rep,
                            const int* __restrict__ ids,
                            const int* __restrict__ aa_len,
                            const int* __restrict__ seq_len) {
    const int blk = blockIdx.x;
    const int b = blk / (Sc / CH);
    const int s0 = (blk % (Sc / CH)) * CH;
    const int L = aa_len[b];
    const int SL = seq_len[b];
    const int* p = ids + b * Ac;

    __shared__ int bound[CH + 1];
    const int t = threadIdx.x;  // 128 threads x 4 cols = 512 cols

    if (t <= CH) {
        int target = s0 + t;
        int lo = 0, hi = L;
        while (lo < hi) { int mid = (lo + hi) >> 1; if (p[mid] < target) lo = mid + 1; else hi = mid; }
        bound[t] = lo;
    }
    __syncthreads();

    // permuted destination columns for this thread's old cols 4t..4t+3
    const int nc0 = kperm(4 * t + 0), nc1 = kperm(4 * t + 1);
    const int nc2 = kperm(4 * t + 2), nc3 = kperm(4 * t + 3);

    const float4* base = reinterpret_cast<const float4*>(rep) + (size_t)b * Ac * (Dc / 4);
    float4 avg = make_float4(0.f, 0.f, 0.f, 0.f);
    int nf_local = 0;

#pragma unroll 1
    for (int i = 0; i < CH; i++) {
        const int st = bound[i], en = bound[i + 1];
        float4 acc = make_float4(0.f, 0.f, 0.f, 0.f);
        int a = st;
        for (; a + 1 < en; a += 2) {
            float4 v0 = base[(size_t)a * (Dc / 4) + t];
            float4 v1 = base[(size_t)(a + 1) * (Dc / 4) + t];
            acc.x += v0.x + v1.x; acc.y += v0.y + v1.y;
            acc.z += v0.z + v1.z; acc.w += v0.w + v1.w;
        }
        if (a < en) {
            float4 v0 = base[(size_t)a * (Dc / 4) + t];
            acc.x += v0.x; acc.y += v0.y; acc.z += v0.z; acc.w += v0.w;
        }
        const int cnt = en - st;
        const float inv = 1.0f / (float)(cnt > 0 ? cnt : 1);
        acc.x = f2tf_f(acc.x * inv); acc.y = f2tf_f(acc.y * inv);
        acc.z = f2tf_f(acc.z * inv); acc.w = f2tf_f(acc.w * inv);

        const int row = b * Sc + s0 + i;
        float* pr = g_pooled + (size_t)row * Dc;
        pr[nc0] = acc.x; pr[nc1] = acc.y; pr[nc2] = acc.z; pr[nc3] = acc.w;

        const bool fill = (cnt > 0) && (s0 + i < SL);
        if (fill) {
            avg.x += acc.x; avg.y += acc.y; avg.z += acc.z; avg.w += acc.w;
            nf_local++;
        }
        if (t == 0) g_filled[row] = fill ? 1 : 0;
    }

    atomicAdd(&g_avgsum[b * Dc + nc0], avg.x);
    atomicAdd(&g_avgsum[b * Dc + nc1], avg.y);
    atomicAdd(&g_avgsum[b * Dc + nc2], avg.z);
    atomicAdd(&g_avgsum[b * Dc + nc3], avg.w);
    if (t == 0) atomicAdd(&g_nfill[b], nf_local);
}

// ---------------- kernel 2: fill unfilled in-range rows with protein avg ---
// avgsum and pooled are both in permuted space -> linear float4 copy is fine.
__global__ void fill_kernel(const int* __restrict__ seq_len) {
    __shared__ int rows[128];
    __shared__ int nr;
    const int t = threadIdx.x;
    if (t == 0) nr = 0;
    __syncthreads();

    const int r = blockIdx.x * 128 + t;
    const int b = r / Sc, s = r % Sc;
    if (!g_filled[r] && s < seq_len[b]) rows[atomicAdd(&nr, 1)] = r;
    __syncthreads();

    for (int i = 0; i < nr; i++) {
        const int rr = rows[i];
        const int bb = rr / Sc;
        const int nf = g_nfill[bb];
        const float inv = 1.0f / (float)(nf > 0 ? nf : 1);
        float4 v;
        v.x = f2tf_f(g_avgsum[bb * Dc + t * 4 + 0] * inv);
        v.y = f2tf_f(g_avgsum[bb * Dc + t * 4 + 1] * inv);
        v.z = f2tf_f(g_avgsum[bb * Dc + t * 4 + 2] * inv);
        v.w = f2tf_f(g_avgsum[bb * Dc + t * 4 + 3] * inv);
        reinterpret_cast<float4*>(g_pooled)[(size_t)rr * (Dc / 4) + t] = v;
    }
}

// ---------------- kernel 3: GEMM out = pooled @ W^T + bias (tf32 mma) ------
// M=16384, N=512, K=512. BM=BN=128, BK=16, 3-stage cp.async, ONE sync/iter.
// 16 warps (512 thr), warp tile 32x32, reg-capped for 2 CTAs/SM (32 warps).
#define BM 128
#define BN 128
#define BK 16
#define PADK 24     // conflict-free for LDS.64 fragment reads (verified per-phase)
#define STG 3
#define GEMM_THREADS 512
#define SMEM_BYTES (STG * (BM + BN) * PADK * 4)

__global__ __launch_bounds__(GEMM_THREADS, 2)
void gemm_kernel(const float* __restrict__ bias, float* __restrict__ out) {
    extern __shared__ float smem[];
    float* AsBase = smem;                         // [STG][BM][PADK]
    float* BsBase = smem + STG * BM * PADK;       // [STG][BN][PADK]

    const int tid = threadIdx.x;
    const int bm = blockIdx.x, bn = blockIdx.y;

    const float* Aori = g_pooled + (size_t)bm * BM * Dc;
    const float* Bori = g_Wtf + (size_t)bn * BN * Dc;

    const int warp = tid >> 5, lane = tid & 31;
    const int wm = warp >> 2, wn = warp & 3;      // 4 x 4 warp grid
    const int m_off = wm * 32, n_off = wn * 32;   // 32x32 warp tile
    const int lr = lane >> 2, lc = lane & 3;

    float c[2][4][4];
#pragma unroll
    for (int mi = 0; mi < 2; mi++)
#pragma unroll
        for (int ni = 0; ni < 4; ni++)
#pragma unroll
            for (int j = 0; j < 4; j++) c[mi][ni][j] = 0.f;

    // A: 128 rows x 16 cols = 512 x 16B chunks; 512 threads -> 1 each. B same.
    const int ld_row = tid >> 2, ld_c4 = tid & 3;
    auto load_tile = [&](int kt, int st) {
        const int k0 = kt * BK;
        float* A = AsBase + st * BM * PADK;
        float* B = BsBase + st * BN * PADK;
        cp_async16cg(A + ld_row * PADK + ld_c4 * 4,
                     Aori + (size_t)ld_row * Dc + k0 + ld_c4 * 4);
        cp_async16cg(B + ld_row * PADK + ld_c4 * 4,
                     Bori + (size_t)ld_row * Dc + k0 + ld_c4 * 4);
        asm volatile("cp.async.commit_group;");
    };

    const int KT = Dc / BK;  // 32
    load_tile(0, 0);
    load_tile(1, 1);

    for (int kt = 0; kt < KT; kt++) {
        asm volatile("cp.async.wait_group 1;");
        __syncthreads();
        if (kt + 2 < KT) load_tile(kt + 2, (kt + 2) % STG);

        const float* A = AsBase + (kt % STG) * BM * PADK;
        const float* B = BsBase + (kt % STG) * BN * PADK;

#pragma unroll
        for (int ks = 0; ks < 2; ks++) {
            const int k0 = ks * 8 + 2 * lc;
            float2 alo[2], ahi[2], bv[4];
#pragma unroll
            for (int mi = 0; mi < 2; mi++) {
                const int r0 = m_off + mi * 16 + lr;
                alo[mi] = *reinterpret_cast<const float2*>(A + r0 * PADK + k0);
                ahi[mi] = *reinterpret_cast<const float2*>(A + (r0 + 8) * PADK + k0);
            }
#pragma unroll
            for (int ni = 0; ni < 4; ni++) {
                const int r0 = n_off + ni * 8 + lr;
                bv[ni] = *reinterpret_cast<const float2*>(B + r0 * PADK + k0);
            }
#pragma unroll
            for (int mi = 0; mi < 2; mi++)
#pragma unroll
                for (int ni = 0; ni < 4; ni++) {
                    MMA_TF32(c[mi][ni][0], c[mi][ni][1], c[mi][ni][2], c[mi][ni][3],
                             __float_as_uint(alo[mi].x), __float_as_uint(ahi[mi].x),
                             __float_as_uint(alo[mi].y), __float_as_uint(ahi[mi].y),
                             __float_as_uint(bv[ni].x), __float_as_uint(bv[ni].y));
                }
        }
        // no trailing sync — STG=3: the stage written by iteration kt+1's load
        // ((kt+3)%3) was consumed in iteration kt-1, ordered by the top barrier.
    }

    // epilogue: + bias, write fp32
    const int row_base = bm * BM + m_off;
    const int col_base = bn * BN + n_off;
#pragma unroll
    for (int mi = 0; mi < 2; mi++) {
#pragma unroll
        for (int ni = 0; ni < 4; ni++) {
            int r0 = row_base + mi * 16 + lr;
            int col = col_base + ni * 8 + 2 * lc;
            float b0 = bias[col], b1 = bias[col + 1];
            float2 v0 = make_float2(c[mi][ni][0] + b0, c[mi][ni][1] + b1);
            float2 v1 = make_float2(c[mi][ni][2] + b0, c[mi][ni][3] + b1);
            *reinterpret_cast<float2*>(out + (size_t)r0 * OUTc + col) = v0;
            *reinterpret_cast<float2*>(out + (size_t)(r0 + 8) * OUTc + col) = v1;
        }
    }
}

// ---------------- launcher -------------------------------------------------
extern "C" void kernel_launch(void* const* d_in, const int* in_sizes, int n_in,
                              void* d_out, int out_size) {
    const float* rep     = (const float*)d_in[0];
    const int*   ids     = (const int*)d_in[1];
    const int*   aa_len  = (const int*)d_in[2];
    const int*   seq_len = (const int*)d_in[3];
    const float* Wm      = (const float*)d_in[4];
    const float* bias    = (const float*)d_in[5];
    float*       out     = (float*)d_out;

    static bool attr_done = false;
    if (!attr_done) {
        cudaFuncSetAttribute(gemm_kernel, cudaFuncAttributeMaxDynamicSharedMemorySize,
                             SMEM_BYTES);
        attr_done = true;
    }

    prep_kernel<<<(OUTc * Dc + 255) / 256, 256>>>(Wm);
    pool_kernel<<<Bc * (Sc / CH), 128>>>(rep, ids, aa_len, seq_len);
    fill_kernel<<<Bc * Sc / 128, 128>>>(seq_len);
    dim3 grid(Bc * Sc / BM, OUTc / BN);
    gemm_kernel<<<grid, GEMM_THREADS, SMEM_BYTES>>>(bias, out);
}